// round 1
// baseline (speedup 1.0000x reference)
#include <cuda_runtime.h>
#include <math.h>

#define SS   512
#define BB   256
#define EMBD 128
#define HIDD 256
#define G4   1024   // 4*HID
#define NCLS 8

// ---------------- device scratch (no allocs allowed) ----------------
// xp[d][s][b][4H] : 2*512*256*1024 floats = 1 GB
__device__ float g_xp[(size_t)2 * SS * BB * G4];
// ping-pong hidden state: g_h[buf][d][b][h]
__device__ float g_h[2 * 2 * BB * HIDD];
// final cell state: g_c[d][b][h]
__device__ float g_c[2 * BB * HIDD];
__device__ unsigned g_bar;

// ---------------- init: zero h buffer 0 + barrier counter ----------------
__global__ void k_init() {
    int i = blockIdx.x * blockDim.x + threadIdx.x;
    if (i < 2 * BB * HIDD) g_h[i] = 0.0f;   // buffer 0 only
    if (i == 0) g_bar = 0u;
}

// ---------------- embedding gather + input projection GEMM ----------------
// grid (2048 row-tiles, 16 col-tiles, 2 dirs), 256 threads, 64KB dyn smem
// Row r = s*256 + b  (so each 64-row tile has a single s). Output 64x64 tile.
__global__ void k_xproj(const int* __restrict__ tokens,
                        const float* __restrict__ emb,
                        const float* __restrict__ Wi_f,
                        const float* __restrict__ Wi_b)
{
    extern __shared__ float sh[];
    float* As = sh;              // [128 k][64 row]  (transposed A)
    float* Bs = sh + 128 * 64;   // [128 k][64 col]

    const int d  = blockIdx.z;
    const float* Wi = d ? Wi_b : Wi_f;
    const int r0 = blockIdx.x * 64;
    const int s  = r0 >> 8;
    const int b0 = r0 & 255;
    const int s_tok = d ? (SS - 1 - s) : s;
    const int ct = blockIdx.y;
    const int tid = threadIdx.x;

    // A: 64 rows x 128 cols of embedded tokens, stored transposed
    for (int idx = tid; idx < 64 * 32; idx += 256) {
        int row = idx >> 5;
        int c4  = idx & 31;
        int tok = tokens[(b0 + row) * SS + s_tok];
        float4 v = reinterpret_cast<const float4*>(emb + (size_t)tok * EMBD)[c4];
        int k = c4 * 4;
        As[(k + 0) * 64 + row] = v.x;
        As[(k + 1) * 64 + row] = v.y;
        As[(k + 2) * 64 + row] = v.z;
        As[(k + 3) * 64 + row] = v.w;
    }
    // B: Wi[k][ct*64 + j]
    for (int idx = tid; idx < 128 * 16; idx += 256) {
        int k  = idx >> 4;
        int j4 = idx & 15;
        float4 v = reinterpret_cast<const float4*>(Wi + (size_t)k * G4 + ct * 64)[j4];
        reinterpret_cast<float4*>(Bs + k * 64)[j4] = v;
    }
    __syncthreads();

    const int tx = tid & 15, ty = tid >> 4;
    float acc[4][4];
#pragma unroll
    for (int i = 0; i < 4; i++)
#pragma unroll
        for (int j = 0; j < 4; j++) acc[i][j] = 0.0f;

#pragma unroll 4
    for (int k = 0; k < 128; k++) {
        float4 a = reinterpret_cast<const float4*>(As + k * 64)[ty];
        float4 w = reinterpret_cast<const float4*>(Bs + k * 64)[tx];
        float av[4] = {a.x, a.y, a.z, a.w};
#pragma unroll
        for (int i = 0; i < 4; i++) {
            acc[i][0] += av[i] * w.x;
            acc[i][1] += av[i] * w.y;
            acc[i][2] += av[i] * w.z;
            acc[i][3] += av[i] * w.w;
        }
    }

    const size_t base = (((size_t)d * SS + s) * BB) * G4;
    const int j0 = ct * 64 + tx * 4;
#pragma unroll
    for (int i = 0; i < 4; i++) {
        int b = b0 + ty * 4 + i;
        float4 o = make_float4(acc[i][0], acc[i][1], acc[i][2], acc[i][3]);
        *reinterpret_cast<float4*>(g_xp + base + (size_t)b * G4 + j0) = o;
    }
}

// ---------------- persistent BiLSTM recurrence ----------------
// 256 CTAs x 256 threads, 98816 B dyn smem, occupancy 2 -> all co-resident.
// CTA: d = blk>>7; b-tile of 32 (rem>>4), jh-tile of 16 (rem&15).
// Thread: jj = tid&15 (jh within tile), bg = tid>>4 -> owns 2 b values.
// Each thread owns cells (d, b0+2bg+{0,1}, jh0+jj); c kept in registers.
__global__ void __launch_bounds__(256, 2)
k_lstm(const float* __restrict__ Wh_f, const float* __restrict__ Wh_b,
       const float* __restrict__ b_f,  const float* __restrict__ b_b)
{
    extern __shared__ float sh[];
    float* Wsh = sh;               // [256 k][64 c]; c = jj*4 + g
    float* Ash = sh + 256 * 64;    // [32 row][260]  (padded h tile)

    const int blk = blockIdx.x;
    const int d   = blk >> 7;
    const int rem = blk & 127;
    const int b0  = (rem >> 4) * 32;
    const int jh0 = (rem & 15) * 16;
    const float* Wh   = d ? Wh_b : Wh_f;
    const float* bias = d ? b_b  : b_f;

    const int tid = threadIdx.x;
    const int jj  = tid & 15;
    const int bg  = tid >> 4;
    const int jh  = jh0 + jj;
    const int b_  = b0 + bg * 2;

    // Load Wh columns for this jh-tile once (reused all 512 steps).
    for (int idx = tid; idx < 256 * 64; idx += 256) {
        int k = idx >> 6, c = idx & 63;
        int jjw = c >> 2, g = c & 3;
        Wsh[k * 64 + c] = Wh[(size_t)k * G4 + g * HIDD + jh0 + jjw];
    }
    float bz[4];
#pragma unroll
    for (int g = 0; g < 4; g++) bz[g] = bias[g * HIDD + jh];

    float c0 = 0.0f, c1 = 0.0f;
    const unsigned nb = gridDim.x;
    __syncthreads();

    for (int s = 0; s < SS; s++) {
        const int cur = s & 1;          // read buffer
        const int nxt = cur ^ 1;        // write buffer

        // prefetch xp for this step (independent of smem phase)
        const size_t xbase = (((size_t)d * SS + s) * BB) * G4;
        float xp0[4], xp1[4];
#pragma unroll
        for (int g = 0; g < 4; g++) {
            xp0[g] = g_xp[xbase + (size_t)(b_ + 0) * G4 + g * HIDD + jh];
            xp1[g] = g_xp[xbase + (size_t)(b_ + 1) * G4 + g * HIDD + jh];
        }

        // stage h tile [32 x 256] into shared
        const float4* h4 = reinterpret_cast<const float4*>(
            g_h + ((cur * 2 + d) * BB + b0) * HIDD);
        for (int idx = tid; idx < 32 * 64; idx += 256) {
            int row = idx >> 6, c4 = idx & 63;
            float4 v = h4[row * 64 + c4];
            *reinterpret_cast<float4*>(Ash + row * 260 + c4 * 4) = v;
        }
        __syncthreads();

        // z = h @ Wh  (two b-rows, 4 gate columns each)
        float z0[4] = {0, 0, 0, 0}, z1[4] = {0, 0, 0, 0};
        const float* a0p = Ash + (bg * 2 + 0) * 260;
        const float* a1p = Ash + (bg * 2 + 1) * 260;
        for (int k = 0; k < 256; k += 4) {
            float4 a0 = *reinterpret_cast<const float4*>(a0p + k);
            float4 a1 = *reinterpret_cast<const float4*>(a1p + k);
            float a0v[4] = {a0.x, a0.y, a0.z, a0.w};
            float a1v[4] = {a1.x, a1.y, a1.z, a1.w};
#pragma unroll
            for (int kk = 0; kk < 4; kk++) {
                float4 w = *reinterpret_cast<const float4*>(Wsh + (k + kk) * 64 + jj * 4);
                z0[0] += a0v[kk] * w.x;  z0[1] += a0v[kk] * w.y;
                z0[2] += a0v[kk] * w.z;  z0[3] += a0v[kk] * w.w;
                z1[0] += a1v[kk] * w.x;  z1[1] += a1v[kk] * w.y;
                z1[2] += a1v[kk] * w.z;  z1[3] += a1v[kk] * w.w;
            }
        }

        // gates (order i,f,g,o) + cell update; c stays in registers
        float zi0 = z0[0] + xp0[0] + bz[0];
        float zf0 = z0[1] + xp0[1] + bz[1];
        float zg0 = z0[2] + xp0[2] + bz[2];
        float zo0 = z0[3] + xp0[3] + bz[3];
        float i0 = 1.0f / (1.0f + expf(-zi0));
        float f0 = 1.0f / (1.0f + expf(-zf0));
        float g0 = tanhf(zg0);
        float o0 = 1.0f / (1.0f + expf(-zo0));
        c0 = f0 * c0 + i0 * g0;
        float h0 = o0 * tanhf(c0);

        float zi1 = z1[0] + xp1[0] + bz[0];
        float zf1 = z1[1] + xp1[1] + bz[1];
        float zg1 = z1[2] + xp1[2] + bz[2];
        float zo1 = z1[3] + xp1[3] + bz[3];
        float i1 = 1.0f / (1.0f + expf(-zi1));
        float f1 = 1.0f / (1.0f + expf(-zf1));
        float g1 = tanhf(zg1);
        float o1 = 1.0f / (1.0f + expf(-zo1));
        c1 = f1 * c1 + i1 * g1;
        float h1 = o1 * tanhf(c1);

        // write new h into the other buffer (no race with readers of cur)
        g_h[((nxt * 2 + d) * BB + b_ + 0) * HIDD + jh] = h0;
        g_h[((nxt * 2 + d) * BB + b_ + 1) * HIDD + jh] = h1;

        // grid barrier (counter monotonic within launch; reset by k_init)
        __threadfence();
        __syncthreads();
        if (tid == 0) {
            atomicAdd(&g_bar, 1u);
            const unsigned target = nb * (unsigned)(s + 1);
            while (atomicAdd(&g_bar, 0u) < target) { }
            __threadfence();
        }
        __syncthreads();
    }

    // final cell state out
    g_c[(d * BB + b_ + 0) * HIDD + jh] = c0;
    g_c[(d * BB + b_ + 1) * HIDD + jh] = c1;
}

// ---------------- classifier: [256, 512] @ [512, 8] + bd ----------------
__global__ void k_cls(const float* __restrict__ Wd,
                      const float* __restrict__ bd,
                      float* __restrict__ out)
{
    const int b = blockIdx.x;
    const int t = threadIdx.x;  // 256 threads == H
    float cf = g_c[(0 * BB + b) * HIDD + t];
    float cb = g_c[(1 * BB + b) * HIDD + t];
    float4 w0a = *reinterpret_cast<const float4*>(Wd + t * 8);
    float4 w0b = *reinterpret_cast<const float4*>(Wd + t * 8 + 4);
    float4 w1a = *reinterpret_cast<const float4*>(Wd + (HIDD + t) * 8);
    float4 w1b = *reinterpret_cast<const float4*>(Wd + (HIDD + t) * 8 + 4);

    float p[8];
    p[0] = cf * w0a.x + cb * w1a.x;  p[1] = cf * w0a.y + cb * w1a.y;
    p[2] = cf * w0a.z + cb * w1a.z;  p[3] = cf * w0a.w + cb * w1a.w;
    p[4] = cf * w0b.x + cb * w1b.x;  p[5] = cf * w0b.y + cb * w1b.y;
    p[6] = cf * w0b.z + cb * w1b.z;  p[7] = cf * w0b.w + cb * w1b.w;

#pragma unroll
    for (int n = 0; n < 8; n++)
#pragma unroll
        for (int off = 16; off > 0; off >>= 1)
            p[n] += __shfl_down_sync(0xFFFFFFFFu, p[n], off);

    __shared__ float sm[8][8];
    const int w = t >> 5, lane = t & 31;
    if (lane == 0) {
#pragma unroll
        for (int n = 0; n < 8; n++) sm[w][n] = p[n];
    }
    __syncthreads();
    if (t < NCLS) {
        float sacc = bd[t];
#pragma unroll
        for (int ww = 0; ww < 8; ww++) sacc += sm[ww][t];
        out[b * NCLS + t] = sacc;
    }
}

// ---------------- launch ----------------
extern "C" void kernel_launch(void* const* d_in, const int* in_sizes, int n_in,
                              void* d_out, int out_size)
{
    const int*   tokens = (const int*)  d_in[0];
    const float* emb    = (const float*)d_in[1];
    const float* Wi_f   = (const float*)d_in[2];
    const float* Wh_f   = (const float*)d_in[3];
    const float* b_f    = (const float*)d_in[4];
    const float* Wi_b   = (const float*)d_in[5];
    const float* Wh_b   = (const float*)d_in[6];
    const float* b_b    = (const float*)d_in[7];
    const float* Wd     = (const float*)d_in[8];
    const float* bd     = (const float*)d_in[9];
    float*       out    = (float*)d_out;
    (void)in_sizes; (void)n_in; (void)out_size;

    static bool attr_done = false;
    if (!attr_done) {
        cudaFuncSetAttribute(k_xproj, cudaFuncAttributeMaxDynamicSharedMemorySize, 65536);
        cudaFuncSetAttribute(k_lstm,  cudaFuncAttributeMaxDynamicSharedMemorySize, 98816);
        attr_done = true;
    }

    k_init<<<512, 256>>>();
    k_xproj<<<dim3(2048, 16, 2), 256, 65536>>>(tokens, emb, Wi_f, Wi_b);
    k_lstm<<<256, 256, 98816>>>(Wh_f, Wh_b, b_f, b_b);
    k_cls<<<256, 256>>>(Wd, bd, out);
}